// round 12
// baseline (speedup 1.0000x reference)
#include <cuda_runtime.h>
#include <cuda_bf16.h>
#include <math.h>
#include <stdint.h>

#define B   64
#define C   256
#define N   20000
#define NPAD 20032          // 313 * 64
#define NT  64
#define KTOP 8
#define PAGE (NT*C)         // 16384 floats per template page
#define GATE_OFF (B*KTOP*NT*C)
#define PARTS 8
#define PARTF 2504          // NPAD / PARTS floats
#define PART4 626           // PARTF / 4

// ---- device scratch ----
__device__ float g_sims[B*NPAD];
__device__ unsigned long long g_cand_k[B*64];
__device__ uint4 g_Whi4[8192];   // 4 chunk-tiles of 256 rows x 64 bf16 (128B rows, XOR-swizzled)
__device__ uint4 g_Wlo4[8192];
__device__ uint32_t g_qhi[8192]; // 4 chunk-tiles of 64 rows x 64 bf16 (normalized q, swizzled) = 32KB
__device__ uint32_t g_qlo[8192];

#define SW128(b) ((b) ^ (((b) >> 3) & 0x70))

__device__ __forceinline__ uint32_t smem_u32(const void* p) {
    uint32_t a;
    asm("{ .reg .u64 t; cvta.to.shared.u64 t, %1; cvt.u32.u64 %0, t; }" : "=r"(a) : "l"(p));
    return a;
}

__device__ __forceinline__ void ldsm_x4(uint32_t* r, uint32_t addr) {
    asm volatile("ldmatrix.sync.aligned.m8n8.x4.shared.b16 {%0,%1,%2,%3}, [%4];"
                 : "=r"(r[0]), "=r"(r[1]), "=r"(r[2]), "=r"(r[3]) : "r"(addr));
}

__device__ __forceinline__ void mma_bf16(float* c, const uint32_t* a, const uint32_t* b) {
    asm volatile(
        "mma.sync.aligned.m16n8k16.row.col.f32.bf16.bf16.f32 "
        "{%0,%1,%2,%3}, {%4,%5,%6,%7}, {%8,%9}, {%0,%1,%2,%3};"
        : "+f"(c[0]), "+f"(c[1]), "+f"(c[2]), "+f"(c[3])
        : "r"(a[0]), "r"(a[1]), "r"(a[2]), "r"(a[3]), "r"(b[0]), "r"(b[1]));
}

__device__ __forceinline__ void cp_async8(uint32_t dst, const void* src) {
    asm volatile("cp.async.ca.shared.global [%0], [%1], 8;" :: "r"(dst), "l"(src));
}
__device__ __forceinline__ void cp_async16(uint32_t dst, const void* src) {
    asm volatile("cp.async.cg.shared.global [%0], [%1], 16;" :: "r"(dst), "l"(src));
}
#define CP_COMMIT() asm volatile("cp.async.commit_group;" ::: "memory")
#define CP_WAIT(n)  asm volatile("cp.async.wait_group %0;" :: "n"(n) : "memory")

// monotone key: bigger value -> bigger key; tie -> lower index bigger key
__device__ __forceinline__ unsigned long long mk_key(float f, int n) {
    int s = __float_as_int(f);
    unsigned u = (unsigned)s ^ (unsigned)((s >> 31) | 0x80000000);
    return ((unsigned long long)u << 32) | (unsigned)(0xffffffffu - (unsigned)n);
}

__device__ __forceinline__ void split_pair(float a, float b, uint32_t& hp, uint32_t& lp) {
    __nv_bfloat16 h0 = __float2bfloat16(a), h1 = __float2bfloat16(b);
    float r0 = a - __bfloat162float(h0), r1 = b - __bfloat162float(h1);
    __nv_bfloat16 l0 = __float2bfloat16(r0), l1 = __float2bfloat16(r1);
    hp = (uint32_t)__bfloat16_as_ushort(h0) | ((uint32_t)__bfloat16_as_ushort(h1) << 16);
    lp = (uint32_t)__bfloat16_as_ushort(l0) | ((uint32_t)__bfloat16_as_ushort(l1) << 16);
}

// ============================================================================
// Kernel 1: W -> bf16 hi/lo pre-swizzled tiles (blocks 0-127)
//           + query normalize -> bf16 hi/lo tiles + gate outputs (block 128)
// ============================================================================
__global__ void prep_all_kernel(const float* __restrict__ wproj,
                                const float* __restrict__ q,
                                const float* __restrict__ gate_logit,
                                float* __restrict__ out)
{
    int tid = threadIdx.x;
    if (blockIdx.x < 128) {
        int p = blockIdx.x * 256 + tid;   // 32768 pairs
        int row = p >> 7, pp = p & 127;
        int k = pp * 2, chunk = pp >> 5, kc = k & 63;
        float2 v = *(const float2*)(wproj + row * C + k);
        uint32_t hp, lp;
        split_pair(v.x, v.y, hp, lp);
        uint32_t off = (uint32_t)SW128(row * 128 + kc * 2);
        uint32_t idx = (uint32_t)chunk * 8192u + (off >> 2);
        ((uint32_t*)g_Whi4)[idx] = hp;
        ((uint32_t*)g_Wlo4)[idx] = lp;
    } else {
        int lane = tid & 31, w = tid >> 5;
        for (int r = w; r < B; r += 8) {
            const float4* qr = (const float4*)(q + r * C);
            float4 a = qr[lane*2], b = qr[lane*2 + 1];
            float ss = a.x*a.x + a.y*a.y + a.z*a.z + a.w*a.w
                     + b.x*b.x + b.y*b.y + b.z*b.z + b.w*b.w;
            #pragma unroll
            for (int o = 16; o > 0; o >>= 1) ss += __shfl_xor_sync(0xffffffffu, ss, o);
            float inv = 1.0f / fmaxf(sqrtf(ss), 1e-12f);
            a.x*=inv; a.y*=inv; a.z*=inv; a.w*=inv;
            b.x*=inv; b.y*=inv; b.z*=inv; b.w*=inv;
            uint32_t chunk = (uint32_t)(lane >> 3);
            uint32_t off = chunk * 8192u
                         + (uint32_t)(r * 128)
                         + ((uint32_t)((lane & 7) * 16) ^ (uint32_t)((r & 7) << 4));
            uint32_t i0 = off >> 2;
            uint32_t hp, lp;
            split_pair(a.x, a.y, hp, lp); g_qhi[i0+0] = hp; g_qlo[i0+0] = lp;
            split_pair(a.z, a.w, hp, lp); g_qhi[i0+1] = hp; g_qlo[i0+1] = lp;
            split_pair(b.x, b.y, hp, lp); g_qhi[i0+2] = hp; g_qlo[i0+2] = lp;
            split_pair(b.z, b.w, hp, lp); g_qhi[i0+3] = hp; g_qlo[i0+3] = lp;
        }
        if (tid < B) {
            float gate = 1.0f / (1.0f + expf(-gate_logit[0]));
            out[GATE_OFF + tid] = gate;
        }
    }
}

// ============================================================================
// Kernel 2: sims = qn @ norm(summaries)^T via mma.sync bf16 hi/lo
// ============================================================================
#define SIM_QHI  0          // 64 x 256 bf16 = 32KB (4 chunk tiles of 8KB)
#define SIM_QLO  32768
#define SIM_BHI  65536      // 128 x 64 bf16 = 16KB (current chunk)
#define SIM_BLO  81920
#define SIM_SSQ  98304      // 128 f32
#define SIM_SINV 98816      // 128 f32
#define SIM_TOTAL 99328

extern __shared__ char s_sm[];

__global__ __launch_bounds__(256, 2) void sims_mma_kernel(const float* __restrict__ summ)
{
    uint32_t smb = smem_u32(s_sm);
    int tid = threadIdx.x, lane = tid & 31, wn = tid >> 5;
    int n0 = blockIdx.x * 128;

    float* ssqS  = (float*)(s_sm + SIM_SSQ);
    float* sinvS = (float*)(s_sm + SIM_SINV);

    // load q tiles (pre-swizzled): 32KB each = 2048 uint4
    #pragma unroll
    for (int i = 0; i < 8; i++) {
        ((uint4*)(s_sm + SIM_QHI))[tid + i * 256] = ((const uint4*)g_qhi)[tid + i * 256];
        ((uint4*)(s_sm + SIM_QLO))[tid + i * 256] = ((const uint4*)g_qlo)[tid + i * 256];
    }
    if (tid < 128) ssqS[tid] = 0.0f;
    __syncthreads();

    uint32_t kbA = (uint32_t)((lane >> 4) << 4);
    uint32_t swA = (uint32_t)((lane & 7) << 4);
    int rB = (lane & 7) + ((lane >> 4) << 3);
    uint32_t boffBase = (uint32_t)((wn * 16 + rB) * 128);
    uint32_t kbB = (uint32_t)(((lane >> 3) & 1) << 4);
    uint32_t swB = (uint32_t)((rB & 7) << 4);

    float acc[4][2][4];
    #pragma unroll
    for (int mt = 0; mt < 4; mt++)
        #pragma unroll
        for (int nt = 0; nt < 2; nt++)
            #pragma unroll
            for (int e = 0; e < 4; e++) acc[mt][nt][e] = 0.0f;

    int frow = tid >> 4;      // 0..15 base row
    int f4i  = tid & 15;      // float4 index within 64-k chunk

    for (int c = 0; c < 4; c++) {
        #pragma unroll
        for (int i = 0; i < 8; i++) {
            int r = frow + i * 16;
            int n = n0 + r;
            float4 v = make_float4(0.f, 0.f, 0.f, 0.f);
            if (n < N) v = *(const float4*)(summ + (size_t)n * C + c * 64 + f4i * 4);
            float s2 = v.x*v.x + v.y*v.y + v.z*v.z + v.w*v.w;
            #pragma unroll
            for (int o = 8; o > 0; o >>= 1) s2 += __shfl_xor_sync(0xffffffffu, s2, o);
            if (f4i == 0) ssqS[r] += s2;
            uint32_t hp0, lp0, hp1, lp1;
            split_pair(v.x, v.y, hp0, lp0);
            split_pair(v.z, v.w, hp1, lp1);
            uint32_t off = (uint32_t)(r * 128) + ((uint32_t)(f4i * 8) ^ (uint32_t)((r & 7) << 4));
            *(uint32_t*)(s_sm + SIM_BHI + off)     = hp0;
            *(uint32_t*)(s_sm + SIM_BHI + off + 4) = hp1;
            *(uint32_t*)(s_sm + SIM_BLO + off)     = lp0;
            *(uint32_t*)(s_sm + SIM_BLO + off + 4) = lp1;
        }
        __syncthreads();

        uint32_t qhiB = smb + SIM_QHI + c * 8192;
        uint32_t qloB = smb + SIM_QLO + c * 8192;
        uint32_t bhiB = smb + SIM_BHI;
        uint32_t bloB = smb + SIM_BLO;

        #pragma unroll
        for (int s = 0; s < 4; s++) {
            uint32_t koffA = ((uint32_t)(s * 32) + kbA) ^ swA;
            uint32_t koffB = ((uint32_t)(s * 32) + kbB) ^ swB;
            uint32_t ah[4][4], al[4][4];
            #pragma unroll
            for (int mt = 0; mt < 4; mt++) {
                uint32_t aoff = (uint32_t)((mt * 16 + (lane & 15)) * 128) + koffA;
                ldsm_x4(ah[mt], qhiB + aoff);
                ldsm_x4(al[mt], qloB + aoff);
            }
            uint32_t bh[4], bl[4];
            ldsm_x4(bh, bhiB + boffBase + koffB);
            ldsm_x4(bl, bloB + boffBase + koffB);
            #pragma unroll
            for (int mt = 0; mt < 4; mt++) {
                mma_bf16(acc[mt][0], ah[mt], &bh[0]);
                mma_bf16(acc[mt][0], ah[mt], &bl[0]);
                mma_bf16(acc[mt][0], al[mt], &bh[0]);
                mma_bf16(acc[mt][1], ah[mt], &bh[2]);
                mma_bf16(acc[mt][1], ah[mt], &bl[2]);
                mma_bf16(acc[mt][1], al[mt], &bh[2]);
            }
        }
        __syncthreads();
    }

    if (tid < 128) sinvS[tid] = 1.0f / fmaxf(sqrtf(ssqS[tid]), 1e-12f);
    __syncthreads();

    #pragma unroll
    for (int mt = 0; mt < 4; mt++) {
        #pragma unroll
        for (int nt = 0; nt < 2; nt++) {
            int nl = wn * 16 + nt * 8 + (lane & 3) * 2;
            int n = n0 + nl;
            if (n + 1 < NPAD) {
                float i0 = sinvS[nl], i1 = sinvS[nl + 1];
                #pragma unroll
                for (int half = 0; half < 2; half++) {
                    int m = mt * 16 + (lane >> 2) + half * 8;
                    float2 o;
                    o.x = (n     < N) ? acc[mt][nt][half*2]     * i0 : -INFINITY;
                    o.y = (n + 1 < N) ? acc[mt][nt][half*2 + 1] * i1 : -INFINITY;
                    *(float2*)(g_sims + (size_t)m * NPAD + n) = o;
                }
            }
        }
    }
}

// ============================================================================
// Kernel 3: partial top-8 per (query, eighth) — prefetched, shuffle select
// ============================================================================
__global__ __launch_bounds__(128) void topk_part_kernel()
{
    __shared__ unsigned long long wk[32];   // 4 warps x 8 winners

    int b = blockIdx.x >> 3, part = blockIdx.x & 7;
    int tid = threadIdx.x, lane = tid & 31, wid = tid >> 5;
    int nbase0 = part * PARTF;
    const float4* rowp = (const float4*)(g_sims + (size_t)b * NPAD + nbase0);

    float4 v[5];
    #pragma unroll
    for (int j = 0; j < 5; j++) {
        int idx = tid + j * 128;
        v[j] = rowp[idx < PART4 ? idx : PART4 - 1];
    }

    unsigned long long k[KTOP];
    #pragma unroll
    for (int j = 0; j < KTOP; j++) k[j] = 0ull;

    #pragma unroll
    for (int j = 0; j < 5; j++) {
        int idx = tid + j * 128;
        if (idx < PART4) {
            int nb = nbase0 + idx * 4;
            float vv[4] = {v[j].x, v[j].y, v[j].z, v[j].w};
            #pragma unroll
            for (int e = 0; e < 4; e++) {
                unsigned long long key = mk_key(vv[e], nb + e);
                if (key > k[KTOP-1]) {
                    int p = KTOP - 1;
                    #pragma unroll
                    for (int jj = KTOP - 1; jj > 0; jj--) {
                        if (key > k[jj-1]) { k[jj] = k[jj-1]; p = jj - 1; }
                        else break;
                    }
                    k[p] = key;
                }
            }
        }
    }

    #pragma unroll
    for (int it = 0; it < KTOP; it++) {
        unsigned long long m = k[0];
        #pragma unroll
        for (int o = 16; o > 0; o >>= 1) {
            unsigned long long t = __shfl_xor_sync(0xffffffffu, m, o);
            if (t > m) m = t;
        }
        if (k[0] == m) {
            #pragma unroll
            for (int j = 0; j < KTOP - 1; j++) k[j] = k[j+1];
            k[KTOP-1] = 0ull;
        }
        if (lane == 0) wk[wid * 8 + it] = m;
    }
    __syncthreads();

    if (wid == 0) {
        unsigned long long a = wk[lane];
        #pragma unroll
        for (int it = 0; it < KTOP; it++) {
            unsigned long long m = a;
            #pragma unroll
            for (int o = 16; o > 0; o >>= 1) {
                unsigned long long t = __shfl_xor_sync(0xffffffffu, m, o);
                if (t > m) m = t;
            }
            if (a == m) a = 0ull;
            if (lane == 0) g_cand_k[b * 64 + part * 8 + it] = m;
        }
    }
}

// ============================================================================
// Kernel 4: pipelined mma.sync fused, M=64 per CTA, 2 CTAs/SM
// merge-topk -> cp.async-staged gather -> (x@W^T + b) -> LN -> gate -> out
// smem ~101KB: single fp32 stage (self-overwrite safe), single W buffer with
// FIFO group discipline: [stage_c, W_c] -> wait(1), convert, commit stage_{c+1},
// wait(1), MMA, commit W_{c+1}.
// ============================================================================
#define FM_XS    0              // 16KB fp32 stage (64 rows x 64k)
#define FM_XHI   16384          // 8KB bf16 hi chunk (64 rows x 128B)
#define FM_XLO   24576          // 8KB bf16 lo chunk
#define FM_WHI   32768          // 32KB (256 rows x 128B, current chunk)
#define FM_WLO   65536          // 32KB
#define FM_PAR   98304          // bias | gamma | beta (256 f32 each)
#define FM_RED   101376         // 4 x 64 float2 = 2KB
#define FM_PAGE  103424         // 1 int
#define FM_TOTAL 103552

extern __shared__ char s_mm[];

__global__ __launch_bounds__(256, 2) void fused_mma_kernel(
    const float* __restrict__ templates,
    const float* __restrict__ bproj,
    const float* __restrict__ gamma_g,
    const float* __restrict__ beta_g,
    const float* __restrict__ gate_logit,
    float* __restrict__ out)
{
    uint32_t smb = smem_u32(s_mm);
    int tid = threadIdx.x, wid = tid >> 5, lane = tid & 31;
    int bid = blockIdx.x;               // b*8 + k
    int wm = wid & 1, wn = wid >> 1;

    float* biasS = (float*)(s_mm + FM_PAR);
    float* gamS  = biasS + 256;
    float* betS  = gamS + 256;
    float2* red2 = (float2*)(s_mm + FM_RED);   // [4][64]
    int*   pageS = (int*)(s_mm + FM_PAGE);
    biasS[tid] = bproj[tid];
    gamS[tid]  = gamma_g[tid];
    betS[tid]  = beta_g[tid];

    // ---- in-block top-k merge: derive this block's page index ----
    if (wid == 0) {
        int qb = bid >> 3;
        int want = bid & 7;
        unsigned long long a = g_cand_k[qb * 64 + lane];
        unsigned long long c = g_cand_k[qb * 64 + lane + 32];
        #pragma unroll
        for (int sel = 0; sel < KTOP; sel++) {
            unsigned long long m = (a > c) ? a : c;
            #pragma unroll
            for (int o = 16; o > 0; o >>= 1) {
                unsigned long long t = __shfl_xor_sync(0xffffffffu, m, o);
                if (t > m) m = t;
            }
            if (a == m) a = 0ull;
            else if (c == m) c = 0ull;
            if (lane == 0 && sel == want)
                pageS[0] = (int)(0xffffffffu - (unsigned)(m & 0xffffffffu));
        }
    }
    __syncthreads();
    int p0 = pageS[0];
    const float* pbase = templates + (size_t)p0 * PAGE;

    // ---- prologue: stage chunk 0 (group A), W chunk 0 (group B) ----
    {
        #pragma unroll
        for (int j = 0; j < 8; j++) {
            int pp = tid + j * 256;
            int row = pp >> 5, kp = pp & 31;
            cp_async8(smb + FM_XS + (uint32_t)pp * 8, pbase + row * C + kp * 2);
        }
        CP_COMMIT();
        #pragma unroll
        for (int i = 0; i < 8; i++) {
            cp_async16(smb + FM_WHI + (uint32_t)(tid + i * 256) * 16,
                       g_Whi4 + tid + i * 256);
            cp_async16(smb + FM_WLO + (uint32_t)(tid + i * 256) * 16,
                       g_Wlo4 + tid + i * 256);
        }
        CP_COMMIT();
    }

    // ldsm address pieces
    int arow0 = wm * 32 + (lane & 15);
    uint32_t aoff0 = (uint32_t)(arow0 * 128);
    uint32_t aoff1 = aoff0 + 16 * 128;
    uint32_t kbA = (uint32_t)((lane >> 4) << 4);
    uint32_t swA = (uint32_t)((lane & 7) << 4);
    int rB = (lane & 7) + ((lane >> 4) << 3);
    uint32_t boffBase = (uint32_t)((wn * 64 + rB) * 128);
    uint32_t kbB = (uint32_t)(((lane >> 3) & 1) << 4);
    uint32_t swB = (uint32_t)((rB & 7) << 4);

    float acc[2][8][4];
    #pragma unroll
    for (int mt = 0; mt < 2; mt++)
        #pragma unroll
        for (int nt = 0; nt < 8; nt++)
            #pragma unroll
            for (int e = 0; e < 4; e++) acc[mt][nt][e] = 0.0f;

    #pragma unroll
    for (int c = 0; c < 4; c++) {
        // stage_c arrived (oldest pending group)
        CP_WAIT(1);

        // convert OWN staged pairs to bf16 hi/lo (own region only)
        #pragma unroll
        for (int j = 0; j < 8; j++) {
            int pp = tid + j * 256;
            int row = pp >> 5, kp = pp & 31;
            float2 v = *(float2*)(s_mm + FM_XS + (uint32_t)pp * 8);
            uint32_t hp, lp;
            split_pair(v.x, v.y, hp, lp);
            uint32_t off = (uint32_t)(row * 128) + (uint32_t)((kp * 4) ^ ((row & 7) << 4));
            *(uint32_t*)(s_mm + FM_XHI + off) = hp;
            *(uint32_t*)(s_mm + FM_XLO + off) = lp;
        }

        // prefetch stage_{c+1} into the SAME buffer (own region already consumed)
        if (c < 3) {
            #pragma unroll
            for (int j = 0; j < 8; j++) {
                int pp = tid + j * 256;
                int row = pp >> 5, kp = pp & 31;
                cp_async8(smb + FM_XS + (uint32_t)pp * 8,
                          pbase + row * C + (c + 1) * 64 + kp * 2);
            }
            CP_COMMIT();
            CP_WAIT(1);     // W_c arrived (stage_{c+1} may fly)
        } else {
            CP_WAIT(0);     // W_3 arrived
        }
        __syncthreads();    // x tiles + W visible to all warps

        uint32_t xbaseH = smb + FM_XHI;
        uint32_t xbaseL = smb + FM_XLO;
        uint32_t wbaseH = smb + FM_WHI;
        uint32_t wbaseL = smb + FM_WLO;

        #pragma unroll
        for (int s = 0; s < 4; s++) {
            uint32_t ka = (uint32_t)(s * 32) + kbA;
            uint32_t koffA = ka ^ swA;
            uint32_t xh[2][4], xl[2][4];
            ldsm_x4(xh[0], xbaseH + aoff0 + koffA);
            ldsm_x4(xh[1], xbaseH + aoff1 + koffA);
            ldsm_x4(xl[0], xbaseL + aoff0 + koffA);
            ldsm_x4(xl[1], xbaseL + aoff1 + koffA);

            uint32_t kb = (uint32_t)(s * 32) + kbB;
            uint32_t koffB = kb ^ swB;
            #pragma unroll
            for (int p = 0; p < 4; p++) {
                uint32_t boff = boffBase + (uint32_t)(p * 16 * 128) + koffB;
                uint32_t wh[4], wl[4];
                ldsm_x4(wh, wbaseH + boff);
                ldsm_x4(wl, wbaseL + boff);
                #pragma unroll
                for (int mt = 0; mt < 2; mt++) {
                    mma_bf16(acc[mt][2*p],   xh[mt], &wh[0]);
                    mma_bf16(acc[mt][2*p],   xh[mt], &wl[0]);
                    mma_bf16(acc[mt][2*p],   xl[mt], &wh[0]);
                    mma_bf16(acc[mt][2*p+1], xh[mt], &wh[2]);
                    mma_bf16(acc[mt][2*p+1], xh[mt], &wl[2]);
                    mma_bf16(acc[mt][2*p+1], xl[mt], &wh[2]);
                }
            }
        }
        __syncthreads();    // MMA done reading XHI/XLO/W before overwrite

        // W chunk c+1 (single buffer, safe after the barrier)
        if (c < 3) {
            #pragma unroll
            for (int i = 0; i < 8; i++) {
                cp_async16(smb + FM_WHI + (uint32_t)(tid + i * 256) * 16,
                           g_Whi4 + (c + 1) * 2048 + tid + i * 256);
                cp_async16(smb + FM_WLO + (uint32_t)(tid + i * 256) * 16,
                           g_Wlo4 + (c + 1) * 2048 + tid + i * 256);
            }
            CP_COMMIT();
        }
    }

    // ---- LayerNorm epilogue ----
    int colb = wn * 64 + (lane & 3) * 2;

    #pragma unroll
    for (int mt = 0; mt < 2; mt++) {
        #pragma unroll
        for (int half = 0; half < 2; half++) {
            float s1 = 0.f, s2 = 0.f;
            #pragma unroll
            for (int nt = 0; nt < 8; nt++) {
                int col0 = colb + nt * 8;
                float h0 = acc[mt][nt][half*2]     + biasS[col0];
                float h1 = acc[mt][nt][half*2 + 1] + biasS[col0 + 1];
                s1 += h0 + h1;
                s2 += h0 * h0 + h1 * h1;
            }
            s1 += __shfl_xor_sync(0xffffffffu, s1, 1);
            s2 += __shfl_xor_sync(0xffffffffu, s2, 1);
            s1 += __shfl_xor_sync(0xffffffffu, s1, 2);
            s2 += __shfl_xor_sync(0xffffffffu, s2, 2);
            if ((lane & 3) == 0) {
                int row = wm * 32 + mt * 16 + half * 8 + (lane >> 2);
                red2[wn * 64 + row] = make_float2(s1, s2);
            }
        }
    }
    __syncthreads();

    float gate = 1.0f / (1.0f + expf(-gate_logit[0]));

    #pragma unroll
    for (int mt = 0; mt < 2; mt++) {
        #pragma unroll
        for (int half = 0; half < 2; half++) {
            int row = wm * 32 + mt * 16 + half * 8 + (lane >> 2);
            float2 r0 = red2[0 * 64 + row];
            float2 r1 = red2[1 * 64 + row];
            float2 r2 = red2[2 * 64 + row];
            float2 r3 = red2[3 * 64 + row];
            float s1 = r0.x + r1.x + r2.x + r3.x;
            float s2 = r0.y + r1.y + r2.y + r3.y;
            float mu   = s1 * (1.0f / 256.0f);
            float var  = s2 * (1.0f / 256.0f) - mu * mu;
            float rstd = rsqrtf(var + 1e-5f);

            float* orow = out + ((size_t)bid * 64 + row) * C;
            #pragma unroll
            for (int nt = 0; nt < 8; nt++) {
                int col0 = colb + nt * 8;
                float h0 = acc[mt][nt][half*2]     + biasS[col0];
                float h1 = acc[mt][nt][half*2 + 1] + biasS[col0 + 1];
                float2 o;
                o.x = ((h0 - mu) * rstd * gamS[col0]     + betS[col0])     * gate;
                o.y = ((h1 - mu) * rstd * gamS[col0 + 1] + betS[col0 + 1]) * gate;
                *(float2*)(orow + col0) = o;
            }
        }
    }
}

// ============================================================================
// launch
// ============================================================================
extern "C" void kernel_launch(void* const* d_in, const int* in_sizes, int n_in,
                              void* d_out, int out_size)
{
    const float* query = (const float*)d_in[0];
    const float* summ  = (const float*)d_in[1];
    const float* templ = (const float*)d_in[2];
    const float* wproj = (const float*)d_in[3];
    const float* bproj = (const float*)d_in[4];
    const float* gamma = (const float*)d_in[5];
    const float* beta  = (const float*)d_in[6];
    const float* glog  = (const float*)d_in[7];
    float* out = (float*)d_out;

    cudaFuncSetAttribute(sims_mma_kernel, cudaFuncAttributeMaxDynamicSharedMemorySize, SIM_TOTAL);
    cudaFuncSetAttribute(fused_mma_kernel, cudaFuncAttributeMaxDynamicSharedMemorySize, FM_TOTAL);

    prep_all_kernel<<<129, 256>>>(wproj, query, glog, out);
    sims_mma_kernel<<<(NPAD + 127) / 128, 256, SIM_TOTAL>>>(summ);
    topk_part_kernel<<<B * PARTS, 128>>>();
    fused_mma_kernel<<<B * KTOP, 256, FM_TOTAL>>>(templ, bproj, gamma, beta, glog, out);
}

// round 14
// speedup vs baseline: 1.1693x; 1.1693x over previous
#include <cuda_runtime.h>
#include <cuda_bf16.h>
#include <cuda_fp16.h>
#include <math.h>
#include <stdint.h>

#define B   64
#define C   256
#define N   20000
#define NPAD 20032          // 313 * 64
#define NT  64
#define KTOP 8
#define PAGE (NT*C)         // 16384 floats per template page
#define GATE_OFF (B*KTOP*NT*C)
#define PARTS 8
#define PARTF 2504          // NPAD / PARTS floats
#define PART4 626           // PARTF / 4

// ---- device scratch ----
__device__ float g_sims[B*NPAD];
__device__ unsigned long long g_cand_k[B*64];
__device__ uint4 g_W4[8192];     // 4 chunk-tiles of 256 rows x 64 fp16 (128B rows, XOR-swizzled)

#define SW128(b) ((b) ^ (((b) >> 3) & 0x70))

__device__ __forceinline__ uint32_t smem_u32(const void* p) {
    uint32_t a;
    asm("{ .reg .u64 t; cvta.to.shared.u64 t, %1; cvt.u32.u64 %0, t; }" : "=r"(a) : "l"(p));
    return a;
}

__device__ __forceinline__ void ldsm_x4(uint32_t* r, uint32_t addr) {
    asm volatile("ldmatrix.sync.aligned.m8n8.x4.shared.b16 {%0,%1,%2,%3}, [%4];"
                 : "=r"(r[0]), "=r"(r[1]), "=r"(r[2]), "=r"(r[3]) : "r"(addr));
}

__device__ __forceinline__ void mma_bf16(float* c, const uint32_t* a, const uint32_t* b) {
    asm volatile(
        "mma.sync.aligned.m16n8k16.row.col.f32.bf16.bf16.f32 "
        "{%0,%1,%2,%3}, {%4,%5,%6,%7}, {%8,%9}, {%0,%1,%2,%3};"
        : "+f"(c[0]), "+f"(c[1]), "+f"(c[2]), "+f"(c[3])
        : "r"(a[0]), "r"(a[1]), "r"(a[2]), "r"(a[3]), "r"(b[0]), "r"(b[1]));
}

__device__ __forceinline__ void mma_f16(float* c, const uint32_t* a, const uint32_t* b) {
    asm volatile(
        "mma.sync.aligned.m16n8k16.row.col.f32.f16.f16.f32 "
        "{%0,%1,%2,%3}, {%4,%5,%6,%7}, {%8,%9}, {%0,%1,%2,%3};"
        : "+f"(c[0]), "+f"(c[1]), "+f"(c[2]), "+f"(c[3])
        : "r"(a[0]), "r"(a[1]), "r"(a[2]), "r"(a[3]), "r"(b[0]), "r"(b[1]));
}

__device__ __forceinline__ void cp_async8(uint32_t dst, const void* src) {
    asm volatile("cp.async.ca.shared.global [%0], [%1], 8;" :: "r"(dst), "l"(src));
}
__device__ __forceinline__ void cp_async16(uint32_t dst, const void* src) {
    asm volatile("cp.async.cg.shared.global [%0], [%1], 16;" :: "r"(dst), "l"(src));
}
#define CP_COMMIT() asm volatile("cp.async.commit_group;" ::: "memory")
#define CP_WAIT(n)  asm volatile("cp.async.wait_group %0;" :: "n"(n) : "memory")

// monotone key: bigger value -> bigger key; tie -> lower index bigger key
__device__ __forceinline__ unsigned long long mk_key(float f, int n) {
    int s = __float_as_int(f);
    unsigned u = (unsigned)s ^ (unsigned)((s >> 31) | 0x80000000);
    return ((unsigned long long)u << 32) | (unsigned)(0xffffffffu - (unsigned)n);
}

// bf16 hi/lo split (for sims path — unchanged semantics)
__device__ __forceinline__ void split_pair(float a, float b, uint32_t& hp, uint32_t& lp) {
    __nv_bfloat16 h0 = __float2bfloat16(a), h1 = __float2bfloat16(b);
    float r0 = a - __bfloat162float(h0), r1 = b - __bfloat162float(h1);
    __nv_bfloat16 l0 = __float2bfloat16(r0), l1 = __float2bfloat16(r1);
    hp = (uint32_t)__bfloat16_as_ushort(h0) | ((uint32_t)__bfloat16_as_ushort(h1) << 16);
    lp = (uint32_t)__bfloat16_as_ushort(l0) | ((uint32_t)__bfloat16_as_ushort(l1) << 16);
}

// fp16 hi/lo split (for fused x path)
__device__ __forceinline__ void split_pair_f16(float a, float b, uint32_t& hp, uint32_t& lp) {
    __half h0 = __float2half_rn(a), h1 = __float2half_rn(b);
    float r0 = a - __half2float(h0), r1 = b - __half2float(h1);
    __half l0 = __float2half_rn(r0), l1 = __float2half_rn(r1);
    hp = (uint32_t)__half_as_ushort(h0) | ((uint32_t)__half_as_ushort(h1) << 16);
    lp = (uint32_t)__half_as_ushort(l0) | ((uint32_t)__half_as_ushort(l1) << 16);
}

// ============================================================================
// Kernel 1: combined  W -> fp16 pre-swizzled tiles (blocks 0-127)
//           + sims = qn @ norm(summaries)^T via bf16 hi/lo mma (blocks 128+)
//             with inline q normalize/convert; block 128 also writes gates.
// ============================================================================
#define SIM_QHI  0          // 64 x 256 bf16 = 32KB (4 chunk tiles of 8KB)
#define SIM_QLO  32768
#define SIM_BHI  65536      // 128 x 64 bf16 = 16KB (current chunk)
#define SIM_BLO  81920
#define SIM_SSQ  98304      // 128 f32
#define SIM_SINV 98816      // 128 f32
#define SIM_TOTAL 99328

extern __shared__ char s_sm[];

__global__ __launch_bounds__(256, 2) void sims_prep_kernel(
    const float* __restrict__ summ,
    const float* __restrict__ wproj,
    const float* __restrict__ q,
    const float* __restrict__ gate_logit,
    float* __restrict__ out)
{
    int tid = threadIdx.x;

    if (blockIdx.x < 128) {
        // ---- W prep: fp16 single, swizzled chunk tiles ----
        int p = blockIdx.x * 256 + tid;   // 32768 pairs
        int row = p >> 7, pp = p & 127;
        int k = pp * 2, chunk = pp >> 5, kc = k & 63;
        float2 v = *(const float2*)(wproj + row * C + k);
        __half h0 = __float2half_rn(v.x), h1 = __float2half_rn(v.y);
        uint32_t hp = (uint32_t)__half_as_ushort(h0) | ((uint32_t)__half_as_ushort(h1) << 16);
        uint32_t off = (uint32_t)SW128(row * 128 + kc * 2);
        ((uint32_t*)g_W4)[(uint32_t)chunk * 8192u + (off >> 2)] = hp;
        return;
    }

    // ---- sims blocks ----
    uint32_t smb = smem_u32(s_sm);
    int lane = tid & 31, wn = tid >> 5;
    int n0 = (blockIdx.x - 128) * 128;

    float* ssqS  = (float*)(s_sm + SIM_SSQ);
    float* sinvS = (float*)(s_sm + SIM_SINV);

    if (blockIdx.x == 128 && tid < B) {
        float gate = 1.0f / (1.0f + expf(-gate_logit[0]));
        out[GATE_OFF + tid] = gate;
    }

    // inline q normalize + bf16 hi/lo convert into smem tiles
    for (int r = wn; r < 64; r += 8) {
        const float4* qr = (const float4*)(q + r * C);
        float4 a = qr[lane*2], b = qr[lane*2 + 1];
        float ss = a.x*a.x + a.y*a.y + a.z*a.z + a.w*a.w
                 + b.x*b.x + b.y*b.y + b.z*b.z + b.w*b.w;
        #pragma unroll
        for (int o = 16; o > 0; o >>= 1) ss += __shfl_xor_sync(0xffffffffu, ss, o);
        float inv = 1.0f / fmaxf(sqrtf(ss), 1e-12f);
        a.x*=inv; a.y*=inv; a.z*=inv; a.w*=inv;
        b.x*=inv; b.y*=inv; b.z*=inv; b.w*=inv;
        uint32_t chunk = (uint32_t)(lane >> 3);
        uint32_t off = chunk * 8192u
                     + (uint32_t)(r * 128)
                     + ((uint32_t)((lane & 7) * 16) ^ (uint32_t)((r & 7) << 4));
        uint32_t hp, lp;
        split_pair(a.x, a.y, hp, lp);
        *(uint32_t*)(s_sm + SIM_QHI + off)      = hp; *(uint32_t*)(s_sm + SIM_QLO + off)      = lp;
        split_pair(a.z, a.w, hp, lp);
        *(uint32_t*)(s_sm + SIM_QHI + off + 4)  = hp; *(uint32_t*)(s_sm + SIM_QLO + off + 4)  = lp;
        split_pair(b.x, b.y, hp, lp);
        *(uint32_t*)(s_sm + SIM_QHI + off + 8)  = hp; *(uint32_t*)(s_sm + SIM_QLO + off + 8)  = lp;
        split_pair(b.z, b.w, hp, lp);
        *(uint32_t*)(s_sm + SIM_QHI + off + 12) = hp; *(uint32_t*)(s_sm + SIM_QLO + off + 12) = lp;
    }
    if (tid < 128) ssqS[tid] = 0.0f;
    __syncthreads();

    uint32_t kbA = (uint32_t)((lane >> 4) << 4);
    uint32_t swA = (uint32_t)((lane & 7) << 4);
    int rB = (lane & 7) + ((lane >> 4) << 3);
    uint32_t boffBase = (uint32_t)((wn * 16 + rB) * 128);
    uint32_t kbB = (uint32_t)(((lane >> 3) & 1) << 4);
    uint32_t swB = (uint32_t)((rB & 7) << 4);

    float acc[4][2][4];
    #pragma unroll
    for (int mt = 0; mt < 4; mt++)
        #pragma unroll
        for (int nt = 0; nt < 2; nt++)
            #pragma unroll
            for (int e = 0; e < 4; e++) acc[mt][nt][e] = 0.0f;

    int frow = tid >> 4;      // 0..15 base row
    int f4i  = tid & 15;      // float4 index within 64-k chunk

    for (int c = 0; c < 4; c++) {
        #pragma unroll
        for (int i = 0; i < 8; i++) {
            int r = frow + i * 16;
            int n = n0 + r;
            float4 v = make_float4(0.f, 0.f, 0.f, 0.f);
            if (n < N) v = *(const float4*)(summ + (size_t)n * C + c * 64 + f4i * 4);
            float s2 = v.x*v.x + v.y*v.y + v.z*v.z + v.w*v.w;
            #pragma unroll
            for (int o = 8; o > 0; o >>= 1) s2 += __shfl_xor_sync(0xffffffffu, s2, o);
            if (f4i == 0) ssqS[r] += s2;
            uint32_t hp0, lp0, hp1, lp1;
            split_pair(v.x, v.y, hp0, lp0);
            split_pair(v.z, v.w, hp1, lp1);
            uint32_t off = (uint32_t)(r * 128) + ((uint32_t)(f4i * 8) ^ (uint32_t)((r & 7) << 4));
            *(uint32_t*)(s_sm + SIM_BHI + off)     = hp0;
            *(uint32_t*)(s_sm + SIM_BHI + off + 4) = hp1;
            *(uint32_t*)(s_sm + SIM_BLO + off)     = lp0;
            *(uint32_t*)(s_sm + SIM_BLO + off + 4) = lp1;
        }
        __syncthreads();

        uint32_t qhiB = smb + SIM_QHI + c * 8192;
        uint32_t qloB = smb + SIM_QLO + c * 8192;
        uint32_t bhiB = smb + SIM_BHI;
        uint32_t bloB = smb + SIM_BLO;

        #pragma unroll
        for (int s = 0; s < 4; s++) {
            uint32_t koffA = ((uint32_t)(s * 32) + kbA) ^ swA;
            uint32_t koffB = ((uint32_t)(s * 32) + kbB) ^ swB;
            uint32_t ah[4][4], al[4][4];
            #pragma unroll
            for (int mt = 0; mt < 4; mt++) {
                uint32_t aoff = (uint32_t)((mt * 16 + (lane & 15)) * 128) + koffA;
                ldsm_x4(ah[mt], qhiB + aoff);
                ldsm_x4(al[mt], qloB + aoff);
            }
            uint32_t bh[4], bl[4];
            ldsm_x4(bh, bhiB + boffBase + koffB);
            ldsm_x4(bl, bloB + boffBase + koffB);
            #pragma unroll
            for (int mt = 0; mt < 4; mt++) {
                mma_bf16(acc[mt][0], ah[mt], &bh[0]);
                mma_bf16(acc[mt][0], ah[mt], &bl[0]);
                mma_bf16(acc[mt][0], al[mt], &bh[0]);
                mma_bf16(acc[mt][1], ah[mt], &bh[2]);
                mma_bf16(acc[mt][1], ah[mt], &bl[2]);
                mma_bf16(acc[mt][1], al[mt], &bh[2]);
            }
        }
        __syncthreads();
    }

    if (tid < 128) sinvS[tid] = 1.0f / fmaxf(sqrtf(ssqS[tid]), 1e-12f);
    __syncthreads();

    #pragma unroll
    for (int mt = 0; mt < 4; mt++) {
        #pragma unroll
        for (int nt = 0; nt < 2; nt++) {
            int nl = wn * 16 + nt * 8 + (lane & 3) * 2;
            int n = n0 + nl;
            if (n + 1 < NPAD) {
                float i0 = sinvS[nl], i1 = sinvS[nl + 1];
                #pragma unroll
                for (int half = 0; half < 2; half++) {
                    int m = mt * 16 + (lane >> 2) + half * 8;
                    float2 o;
                    o.x = (n     < N) ? acc[mt][nt][half*2]     * i0 : -INFINITY;
                    o.y = (n + 1 < N) ? acc[mt][nt][half*2 + 1] * i1 : -INFINITY;
                    *(float2*)(g_sims + (size_t)m * NPAD + n) = o;
                }
            }
        }
    }
}

// ============================================================================
// Kernel 2: partial top-8 per (query, eighth) — prefetched, shuffle select
// ============================================================================
__global__ __launch_bounds__(128) void topk_part_kernel()
{
    __shared__ unsigned long long wk[32];   // 4 warps x 8 winners

    int b = blockIdx.x >> 3, part = blockIdx.x & 7;
    int tid = threadIdx.x, lane = tid & 31, wid = tid >> 5;
    int nbase0 = part * PARTF;
    const float4* rowp = (const float4*)(g_sims + (size_t)b * NPAD + nbase0);

    float4 v[5];
    #pragma unroll
    for (int j = 0; j < 5; j++) {
        int idx = tid + j * 128;
        v[j] = rowp[idx < PART4 ? idx : PART4 - 1];
    }

    unsigned long long k[KTOP];
    #pragma unroll
    for (int j = 0; j < KTOP; j++) k[j] = 0ull;

    #pragma unroll
    for (int j = 0; j < 5; j++) {
        int idx = tid + j * 128;
        if (idx < PART4) {
            int nb = nbase0 + idx * 4;
            float vv[4] = {v[j].x, v[j].y, v[j].z, v[j].w};
            #pragma unroll
            for (int e = 0; e < 4; e++) {
                unsigned long long key = mk_key(vv[e], nb + e);
                if (key > k[KTOP-1]) {
                    int p = KTOP - 1;
                    #pragma unroll
                    for (int jj = KTOP - 1; jj > 0; jj--) {
                        if (key > k[jj-1]) { k[jj] = k[jj-1]; p = jj - 1; }
                        else break;
                    }
                    k[p] = key;
                }
            }
        }
    }

    #pragma unroll
    for (int it = 0; it < KTOP; it++) {
        unsigned long long m = k[0];
        #pragma unroll
        for (int o = 16; o > 0; o >>= 1) {
            unsigned long long t = __shfl_xor_sync(0xffffffffu, m, o);
            if (t > m) m = t;
        }
        if (k[0] == m) {
            #pragma unroll
            for (int j = 0; j < KTOP - 1; j++) k[j] = k[j+1];
            k[KTOP-1] = 0ull;
        }
        if (lane == 0) wk[wid * 8 + it] = m;
    }
    __syncthreads();

    if (wid == 0) {
        unsigned long long a = wk[lane];
        #pragma unroll
        for (int it = 0; it < KTOP; it++) {
            unsigned long long m = a;
            #pragma unroll
            for (int o = 16; o > 0; o >>= 1) {
                unsigned long long t = __shfl_xor_sync(0xffffffffu, m, o);
                if (t > m) m = t;
            }
            if (a == m) a = 0ull;
            if (lane == 0) g_cand_k[b * 64 + part * 8 + it] = m;
        }
    }
}

// ============================================================================
// Kernel 3: pipelined fused, fp16 2-term (x split, W single), M=64/CTA
// merge-topk -> cp.async-staged gather -> (x@W^T + b) -> LN -> gate -> out
// ============================================================================
#define FM_XS    0              // 16KB fp32 stage (64 rows x 64k)
#define FM_XHI   16384          // 8KB fp16 hi chunk (64 rows x 128B)
#define FM_XLO   24576          // 8KB fp16 lo chunk
#define FM_W     32768          // 32KB (256 rows x 128B fp16, current chunk)
#define FM_PAR   65536          // bias | gamma | beta (256 f32 each)
#define FM_RED   68608          // 4 x 64 float2 = 2KB
#define FM_PAGE  70656          // 1 int
#define FM_TOTAL 70784

extern __shared__ char s_mm[];

__global__ __launch_bounds__(256, 2) void fused_mma_kernel(
    const float* __restrict__ templates,
    const float* __restrict__ bproj,
    const float* __restrict__ gamma_g,
    const float* __restrict__ beta_g,
    const float* __restrict__ gate_logit,
    float* __restrict__ out)
{
    uint32_t smb = smem_u32(s_mm);
    int tid = threadIdx.x, wid = tid >> 5, lane = tid & 31;
    int bid = blockIdx.x;               // b*8 + k
    int wm = wid & 1, wn = wid >> 1;

    float* biasS = (float*)(s_mm + FM_PAR);
    float* gamS  = biasS + 256;
    float* betS  = gamS + 256;
    float2* red2 = (float2*)(s_mm + FM_RED);   // [4][64]
    int*   pageS = (int*)(s_mm + FM_PAGE);
    biasS[tid] = bproj[tid];
    gamS[tid]  = gamma_g[tid];
    betS[tid]  = beta_g[tid];

    // ---- in-block top-k merge: derive this block's page index ----
    if (wid == 0) {
        int qb = bid >> 3;
        int want = bid & 7;
        unsigned long long a = g_cand_k[qb * 64 + lane];
        unsigned long long c = g_cand_k[qb * 64 + lane + 32];
        #pragma unroll
        for (int sel = 0; sel < KTOP; sel++) {
            unsigned long long m = (a > c) ? a : c;
            #pragma unroll
            for (int o = 16; o > 0; o >>= 1) {
                unsigned long long t = __shfl_xor_sync(0xffffffffu, m, o);
                if (t > m) m = t;
            }
            if (a == m) a = 0ull;
            else if (c == m) c = 0ull;
            if (lane == 0 && sel == want)
                pageS[0] = (int)(0xffffffffu - (unsigned)(m & 0xffffffffu));
        }
    }
    __syncthreads();
    int p0 = pageS[0];
    const float* pbase = templates + (size_t)p0 * PAGE;

    // ---- prologue: stage chunk 0 (group A), W chunk 0 (group B) ----
    {
        #pragma unroll
        for (int j = 0; j < 8; j++) {
            int pp = tid + j * 256;
            int row = pp >> 5, kp = pp & 31;
            cp_async8(smb + FM_XS + (uint32_t)pp * 8, pbase + row * C + kp * 2);
        }
        CP_COMMIT();
        #pragma unroll
        for (int i = 0; i < 8; i++) {
            cp_async16(smb + FM_W + (uint32_t)(tid + i * 256) * 16,
                       g_W4 + tid + i * 256);
        }
        CP_COMMIT();
    }

    // ldsm address pieces
    int arow0 = wm * 32 + (lane & 15);
    uint32_t aoff0 = (uint32_t)(arow0 * 128);
    uint32_t aoff1 = aoff0 + 16 * 128;
    uint32_t kbA = (uint32_t)((lane >> 4) << 4);
    uint32_t swA = (uint32_t)((lane & 7) << 4);
    int rB = (lane & 7) + ((lane >> 4) << 3);
    uint32_t boffBase = (uint32_t)((wn * 64 + rB) * 128);
    uint32_t kbB = (uint32_t)(((lane >> 3) & 1) << 4);
    uint32_t swB = (uint32_t)((rB & 7) << 4);

    float acc[2][8][4];
    #pragma unroll
    for (int mt = 0; mt < 2; mt++)
        #pragma unroll
        for (int nt = 0; nt < 8; nt++)
            #pragma unroll
            for (int e = 0; e < 4; e++) acc[mt][nt][e] = 0.0f;

    #pragma unroll
    for (int c = 0; c < 4; c++) {
        // stage_c arrived (oldest pending group)
        CP_WAIT(1);

        // convert OWN staged pairs to fp16 hi/lo (own region only)
        #pragma unroll
        for (int j = 0; j < 8; j++) {
            int pp = tid + j * 256;
            int row = pp >> 5, kp = pp & 31;
            float2 v = *(float2*)(s_mm + FM_XS + (uint32_t)pp * 8);
            uint32_t hp, lp;
            split_pair_f16(v.x, v.y, hp, lp);
            uint32_t off = (uint32_t)(row * 128) + (uint32_t)((kp * 4) ^ ((row & 7) << 4));
            *(uint32_t*)(s_mm + FM_XHI + off) = hp;
            *(uint32_t*)(s_mm + FM_XLO + off) = lp;
        }

        // prefetch stage_{c+1} into the SAME buffer (own region already consumed)
        if (c < 3) {
            #pragma unroll
            for (int j = 0; j < 8; j++) {
                int pp = tid + j * 256;
                int row = pp >> 5, kp = pp & 31;
                cp_async8(smb + FM_XS + (uint32_t)pp * 8,
                          pbase + row * C + (c + 1) * 64 + kp * 2);
            }
            CP_COMMIT();
            CP_WAIT(1);     // W_c arrived (stage_{c+1} may fly)
        } else {
            CP_WAIT(0);     // W_3 arrived
        }
        __syncthreads();    // x tiles + W visible to all warps

        uint32_t xbaseH = smb + FM_XHI;
        uint32_t xbaseL = smb + FM_XLO;
        uint32_t wbase  = smb + FM_W;

        #pragma unroll
        for (int s = 0; s < 4; s++) {
            uint32_t ka = (uint32_t)(s * 32) + kbA;
            uint32_t koffA = ka ^ swA;
            uint32_t xh[2][4], xl[2][4];
            ldsm_x4(xh[0], xbaseH + aoff0 + koffA);
            ldsm_x4(xh[1], xbaseH + aoff1 + koffA);
            ldsm_x4(xl[0], xbaseL + aoff0 + koffA);
            ldsm_x4(xl[1], xbaseL + aoff1 + koffA);

            uint32_t kb = (uint32_t)(s * 32) + kbB;
            uint32_t koffB = kb ^ swB;
            #pragma unroll
            for (int p = 0; p < 4; p++) {
                uint32_t boff = boffBase + (uint32_t)(p * 16 * 128) + koffB;
                uint32_t wh[4];
                ldsm_x4(wh, wbase + boff);
                #pragma unroll
                for (int mt = 0; mt < 2; mt++) {
                    mma_f16(acc[mt][2*p],   xh[mt], &wh[0]);
                    mma_f16(acc[mt][2*p],   xl[mt], &wh[0]);
                    mma_f16(acc[mt][2*p+1], xh[mt], &wh[2]);
                    mma_f16(acc[mt][2*p+1], xl[mt], &wh[2]);
                }
            }
        }
        __syncthreads();    // MMA done reading XHI/XLO/W before overwrite

        // W chunk c+1 (single buffer, safe after the barrier)
        if (c < 3) {
            #pragma unroll
            for (int i = 0; i < 8; i++) {
                cp_async16(smb + FM_W + (uint32_t)(tid + i * 256) * 16,
                           g_W4 + (c + 1) * 2048 + tid + i * 256);
            }
            CP_COMMIT();
        }
    }

    // ---- LayerNorm epilogue ----
    int colb = wn * 64 + (lane & 3) * 2;

    #pragma unroll
    for (int mt = 0; mt < 2; mt++) {
        #pragma unroll
        for (int half = 0; half < 2; half++) {
            float s1 = 0.f, s2 = 0.f;
            #pragma unroll
            for (int nt = 0; nt < 8; nt++) {
                int col0 = colb + nt * 8;
                float h0 = acc[mt][nt][half*2]     + biasS[col0];
                float h1 = acc[mt][nt][half*2 + 1] + biasS[col0 + 1];
                s1 += h0 + h1;
                s2 += h0 * h0 + h1 * h1;
            }
            s1 += __shfl_xor_sync(0xffffffffu, s1, 1);
            s2 += __shfl_xor_sync(0xffffffffu, s2, 1);
            s1 += __shfl_xor_sync(0xffffffffu, s1, 2);
            s2 += __shfl_xor_sync(0xffffffffu, s2, 2);
            if ((lane & 3) == 0) {
                int row = wm * 32 + mt * 16 + half * 8 + (lane >> 2);
                red2[wn * 64 + row] = make_float2(s1, s2);
            }
        }
    }
    __syncthreads();

    float gate = 1.0f / (1.0f + expf(-gate_logit[0]));

    #pragma unroll
    for (int mt = 0; mt < 2; mt++) {
        #pragma unroll
        for (int half = 0; half < 2; half++) {
            int row = wm * 32 + mt * 16 + half * 8 + (lane >> 2);
            float2 r0 = red2[0 * 64 + row];
            float2 r1 = red2[1 * 64 + row];
            float2 r2 = red2[2 * 64 + row];
            float2 r3 = red2[3 * 64 + row];
            float s1 = r0.x + r1.x + r2.x + r3.x;
            float s2 = r0.y + r1.y + r2.y + r3.y;
            float mu   = s1 * (1.0f / 256.0f);
            float var  = s2 * (1.0f / 256.0f) - mu * mu;
            float rstd = rsqrtf(var + 1e-5f);

            float* orow = out + ((size_t)bid * 64 + row) * C;
            #pragma unroll
            for (int nt = 0; nt < 8; nt++) {
                int col0 = colb + nt * 8;
                float h0 = acc[mt][nt][half*2]     + biasS[col0];
                float h1 = acc[mt][nt][half*2 + 1] + biasS[col0 + 1];
                float2 o;
                o.x = ((h0 - mu) * rstd * gamS[col0]     + betS[col0])     * gate;
                o.y = ((h1 - mu) * rstd * gamS[col0 + 1] + betS[col0 + 1]) * gate;
                *(float2*)(orow + col0) = o;
            }
        }
    }
}

// ============================================================================
// launch
// ============================================================================
extern "C" void kernel_launch(void* const* d_in, const int* in_sizes, int n_in,
                              void* d_out, int out_size)
{
    const float* query = (const float*)d_in[0];
    const float* summ  = (const float*)d_in[1];
    const float* templ = (const float*)d_in[2];
    const float* wproj = (const float*)d_in[3];
    const float* bproj = (const float*)d_in[4];
    const float* gamma = (const float*)d_in[5];
    const float* beta  = (const float*)d_in[6];
    const float* glog  = (const float*)d_in[7];
    float* out = (float*)d_out;

    cudaFuncSetAttribute(sims_prep_kernel, cudaFuncAttributeMaxDynamicSharedMemorySize, SIM_TOTAL);
    cudaFuncSetAttribute(fused_mma_kernel, cudaFuncAttributeMaxDynamicSharedMemorySize, FM_TOTAL);

    sims_prep_kernel<<<128 + (NPAD + 127) / 128, 256, SIM_TOTAL>>>(summ, wproj, query, glog, out);
    topk_part_kernel<<<B * PARTS, 128>>>();
    fused_mma_kernel<<<B * KTOP, 256, FM_TOTAL>>>(templ, bproj, gamma, beta, glog, out);
}